// round 13
// baseline (speedup 1.0000x reference)
#include <cuda_runtime.h>
#include <cuda_fp16.h>
#include <math.h>
#include <stdint.h>

#define N      8192
#define INCH   256
#define OUTCH  64
#define NSPLIT 8
#define JSPAN  (N / NSPLIT)     // 1024
#define TIROWS 128
#define NIT    (JSPAN / 64)     // 16 iterations (64 j each)
#define ONES16 0x3C003C00u
#define STAGES 4

// ---------------- device scratch ----------------
__device__ float    g_Wh[N * OUTCH];
__device__ float    g_s1[N], g_s2[N];
__device__ unsigned g_m2u;                        // encoded float max (idempotent)
__device__ __align__(16) uint2 g_arh[N];          // per-row (A1 h2, Ah h2) broadcast
__device__ __align__(16) uint2 g_eph[N / 2];      // per j-pair (E1 h2, Eh h2)
__device__ unsigned g_adjT[(N / 32) * N];         // bit-packed adj [word][row]
// B in mma-fragment layout: [kbg][nt 0..7][lane 0..31] x uint2(b0,b1) fp16x2
__device__ __align__(16) uint2 g_Bfrag[(N / 16) * 8 * 32];
__device__ float    g_part[NSPLIT * N * OUTCH];
__device__ float    g_Zp[NSPLIT * N];

__device__ __forceinline__ unsigned fenc(float f) {
    unsigned u = __float_as_uint(f);
    return (u & 0x80000000u) ? ~u : (u | 0x80000000u);
}
__device__ __forceinline__ float fdec(unsigned k) {
    return __uint_as_float((k & 0x80000000u) ? (k ^ 0x80000000u) : ~k);
}
__device__ __forceinline__ uint32_t f16x2_pack(float lo, float hi) {
    uint32_t r;
    asm("cvt.rn.f16x2.f32 %0, %1, %2;" : "=r"(r) : "f"(hi), "f"(lo));
    return r;
}
__device__ __forceinline__ uint32_t hmul2(uint32_t a, uint32_t b) {
    uint32_t d;
    asm("mul.f16x2 %0, %1, %2;" : "=r"(d) : "r"(a), "r"(b));
    return d;
}
__device__ __forceinline__ uint32_t hmax2(uint32_t a, uint32_t b) {
    uint32_t d;
    asm("max.f16x2 %0, %1, %2;" : "=r"(d) : "r"(a), "r"(b));
    return d;
}
// expand adjacency bit-pair (jloc, jloc+1) into two 16-bit lane masks via PRMT sign mode
__device__ __forceinline__ uint32_t mk_mask2(unsigned aw, int jloc) {
    const uint32_t y = (aw >> jloc) & 3u;
    const uint32_t x = y * 0x4080u;          // byte0 MSB = bit0, byte1 MSB = bit1
    uint32_t m;
    asm("prmt.b32 %0, %1, %2, 0x9988;" : "=r"(m) : "r"(x), "r"(0u));
    return m;
}
__device__ __forceinline__ uint32_t smem_u32(const void* p) {
    uint32_t a;
    asm("{ .reg .u64 t; cvta.to.shared.u64 t, %1; cvt.u32.u64 %0, t; }" : "=r"(a) : "l"(p));
    return a;
}

#define MMA16816(d, a0, a1, a2, a3, b0, b1)                                       \
    asm volatile("mma.sync.aligned.m16n8k16.row.col.f32.f16.f16.f32 "            \
        "{%0,%1,%2,%3}, {%4,%5,%6,%7}, {%8,%9}, {%0,%1,%2,%3};"                  \
        : "+f"((d)[0]), "+f"((d)[1]), "+f"((d)[2]), "+f"((d)[3])                  \
        : "r"(a0), "r"(a1), "r"(a2), "r"(a3), "r"(b0), "r"(b1))

#define CP16(dst, src) \
    asm volatile("cp.async.cg.shared.global [%0], [%1], 16;" :: "r"(dst), "l"(src) : "memory")
#define CP_COMMIT()   asm volatile("cp.async.commit_group;" ::: "memory")
#define CP_WAIT(nn)   asm volatile("cp.async.wait_group %0;" :: "n"(nn) : "memory")

// ================= K0: fused wh-GEMM (blocks 0..511) + adj bitpack (rest) ======
#define WH_BLOCKS   (N / 16)          // 512
#define BP_BLOCKS   (8 * (N / 8))     // 8192

__global__ __launch_bounds__(256) void fused0_kernel(const float* __restrict__ h,
                                                     const float* __restrict__ W,
                                                     const int* __restrict__ adj) {
    __shared__ __align__(16) char smraw[64 * 64 * 4];
    const int t = threadIdx.x;
    const int bid = blockIdx.x;

    if (bid < WH_BLOCKS) {
        float* Ws = reinterpret_cast<float*>(smraw);
        const int col = t & 63;
        const int rowgrp = t >> 6;
        const int i0 = bid * 16;

        float acc[4] = {0.f, 0.f, 0.f, 0.f};
        for (int kc = 0; kc < 4; kc++) {
            __syncthreads();
            float4* wsv = reinterpret_cast<float4*>(Ws);
            const float4* wgv = reinterpret_cast<const float4*>(W + kc * 64 * 64);
            #pragma unroll
            for (int q = 0; q < 4; q++) wsv[t + 256 * q] = wgv[t + 256 * q];
            __syncthreads();

            #pragma unroll 4
            for (int kk = 0; kk < 64; kk += 4) {
                const int k = kc * 64 + kk;
                const float w0 = Ws[(kk + 0) * 64 + col];
                const float w1 = Ws[(kk + 1) * 64 + col];
                const float w2 = Ws[(kk + 2) * 64 + col];
                const float w3 = Ws[(kk + 3) * 64 + col];
                #pragma unroll
                for (int rr = 0; rr < 4; rr++) {
                    const int rrow = i0 + rowgrp * 4 + rr;
                    const float4 hv = *reinterpret_cast<const float4*>(h + (size_t)rrow * INCH + k);
                    acc[rr] += hv.x * w0 + hv.y * w1 + hv.z * w2 + hv.w * w3;
                }
            }
        }
        #pragma unroll
        for (int rr = 0; rr < 4; rr++)
            g_Wh[(size_t)(i0 + rowgrp * 4 + rr) * OUTCH + col] = acc[rr];

        // B fragment (single fp16), k = row index, n = col
        const int kbg = i0 >> 4;
        const int nt = col >> 3;
        const int g = col & 7;
        uint32_t* bf = reinterpret_cast<uint32_t*>(g_Bfrag);
        #pragma unroll
        for (int p = 0; p < 2; p++) {
            const int kp = rowgrp * 4 + 2 * p;
            const int slotbase = (kp < 8) ? 0 : 1;
            const int tq = (kp < 8) ? (kp >> 1) : ((kp - 8) >> 1);
            const int lane = g * 4 + tq;
            const uint32_t hw = f16x2_pack(acc[2 * p], acc[2 * p + 1]);
            bf[(((size_t)(kbg * 8 + nt) * 32 + lane) << 1) + slotbase] = hw;
        }
    } else {
        unsigned* sw = reinterpret_cast<unsigned*>(smraw);   // [32 words][9]
        const int b = bid - WH_BLOCKS;
        const int bx = b & 7;
        const int ry = b >> 3;
        const int wi = t >> 5, lane = t & 31;
        const int r = ry * 8 + wi;
        const int* rowp = adj + (size_t)r * N + (size_t)bx * 1024;
        #pragma unroll
        for (int ww = 0; ww < 32; ww++) {
            const int v = rowp[ww * 32 + lane];
            const unsigned word = __ballot_sync(0xffffffffu, v != 0);
            if (lane == 0) sw[ww * 9 + wi] = word;
        }
        __syncthreads();
        const int word = t >> 3, row = t & 7;
        g_adjT[(size_t)(bx * 32 + word) * N + ry * 8 + row] = sw[word * 9 + row];
    }
}

// ================= K2: s1/s2 + encoded global max of s2 =================
__global__ __launch_bounds__(256) void s_kernel(const float* __restrict__ a) {
    __shared__ float sm2[8];
    const int wid = threadIdx.x >> 5;
    const int lane = threadIdx.x & 31;
    const int i = blockIdx.x * 8 + wid;
    const float v1 = g_Wh[(size_t)i * 64 + lane];
    const float v2 = g_Wh[(size_t)i * 64 + 32 + lane];
    float p1 = v1 * a[lane] + v2 * a[32 + lane];
    float p2 = v1 * a[64 + lane] + v2 * a[96 + lane];
    #pragma unroll
    for (int o = 16; o; o >>= 1) {
        p1 += __shfl_xor_sync(0xffffffffu, p1, o);
        p2 += __shfl_xor_sync(0xffffffffu, p2, o);
    }
    if (lane == 0) { g_s1[i] = p1; g_s2[i] = p2; sm2[wid] = p2; }
    __syncthreads();
    if (threadIdx.x == 0) {
        float m2 = sm2[0];
        #pragma unroll
        for (int q = 1; q < 8; q++) m2 = fmaxf(m2, sm2[q]);
        atomicMax(&g_m2u, fenc(m2));
    }
}

// ================= K3: per-node half2 factors (per-row normalized) =============
__global__ __launch_bounds__(256) void epack_kernel() {
    const int i = blockIdx.x * 256 + threadIdx.x;
    const float M2 = fdec(g_m2u);
    if (i < N) {
        const float X = g_s1[i] + M2;
        const float Lrow = (X >= 0.f) ? X : 0.5f * X;
        const float A1 = expf(X - Lrow);
        const float Ah = expf(0.5f * X - Lrow);
        g_arh[i] = make_uint2(f16x2_pack(A1, A1), f16x2_pack(Ah, Ah));
    }
    if (i < N / 2) {
        const float s2a = g_s2[2 * i] - M2, s2b = g_s2[2 * i + 1] - M2;
        g_eph[i] = make_uint2(f16x2_pack(expf(s2a), expf(s2b)),
                              f16x2_pack(expf(0.5f * s2a), expf(0.5f * s2b)));
    }
}

// ================= K4: half2 weight-gen + fp16 mma, 3 CTA/SM =================
__global__ __launch_bounds__(256, 3) void gat_mma() {
    __shared__ __align__(16) uint2 smB[STAGES * 1024];   // 4 x 8KB B buffers
    __shared__ __align__(16) uint2 smE[STAGES * 32];     // 4 x 256B ep buffers

    const int t = threadIdx.x;
    const int w = t >> 5, lane = t & 31;
    const int g = lane >> 2, tq = lane & 3;
    const int split = blockIdx.x;
    const int rowbase = blockIdx.y * TIROWS;
    const int jbase = split * JSPAN;
    const int kbg0 = jbase >> 4;
    const int wb0 = jbase >> 5;

    const int r1 = rowbase + w * 16 + g;
    const int r2 = r1 + 8;
    const uint2 ar1 = g_arh[r1];
    const uint2 ar2 = g_arh[r2];

    float acc[8][4];
    #pragma unroll
    for (int nt = 0; nt < 8; nt++)
        #pragma unroll
        for (int c = 0; c < 4; c++) acc[nt][c] = 0.f;
    float accz[4] = {0.f, 0.f, 0.f, 0.f};

    // adj words: 2 per row per 64-j iteration (reloaded at iteration end)
    unsigned c1a = g_adjT[(size_t)wb0 * N + r1];
    unsigned c1b = g_adjT[(size_t)(wb0 + 1) * N + r1];
    unsigned c2a = g_adjT[(size_t)wb0 * N + r2];
    unsigned c2b = g_adjT[(size_t)(wb0 + 1) * N + r2];

    const uint4* bsrc4 = reinterpret_cast<const uint4*>(g_Bfrag + (size_t)kbg0 * 256);
    const uint4* esrc4 = reinterpret_cast<const uint4*>(g_eph + jbase / 2);
    const uint32_t sbB = smem_u32(smB);
    const uint32_t sbE = smem_u32(smE);

    // prologue: stages 0..2
    #pragma unroll
    for (int s = 0; s < STAGES - 1; s++) {
        CP16(sbB + s * 8192 + t * 16, bsrc4 + (size_t)s * 512 + t);
        CP16(sbB + s * 8192 + 4096 + t * 16, bsrc4 + (size_t)s * 512 + 256 + t);
        if (t < 16) CP16(sbE + s * 256 + t * 16, esrc4 + s * 16 + t);
        CP_COMMIT();
    }

    for (int hh = 0; hh < NIT; hh++) {
        const int slot = hh % STAGES;
        CP_WAIT(2);
        __syncthreads();

        // issue stage hh+3 into slot consumed at hh-1
        if (hh + STAGES - 1 < NIT) {
            const int hs = hh + STAGES - 1;
            const int ns = hs % STAGES;
            CP16(sbB + ns * 8192 + t * 16, bsrc4 + (size_t)hs * 512 + t);
            CP16(sbB + ns * 8192 + 4096 + t * 16, bsrc4 + (size_t)hs * 512 + 256 + t);
            if (t < 16) CP16(sbE + ns * 256 + t * 16, esrc4 + hs * 16 + t);
        }
        CP_COMMIT();

        const uint2* bs = smB + slot * 1024;
        const uint2* es = smE + slot * 32;

        #pragma unroll
        for (int q = 0; q < 2; q++) {
            const unsigned aw1 = q ? c1b : c1a;
            const unsigned aw2 = q ? c2b : c2a;
            #pragma unroll
            for (int kb = 0; kb < 2; kb++) {
                uint32_t av[4];
                #pragma unroll
                for (int pr = 0; pr < 2; pr++) {
                    const int jloc = kb * 16 + pr * 8 + 2 * tq;
                    const uint2 e = es[q * 16 + kb * 8 + pr * 4 + tq];
                    const uint32_t w1 = hmax2(hmul2(ar1.x, e.x), hmul2(ar1.y, e.y));
                    const uint32_t w2 = hmax2(hmul2(ar2.x, e.x), hmul2(ar2.y, e.y));
                    av[2 * pr + 0] = w1 & mk_mask2(aw1, jloc);
                    av[2 * pr + 1] = w2 & mk_mask2(aw2, jloc);
                }
                #pragma unroll
                for (int nt = 0; nt < 8; nt++) {
                    const uint2 b = bs[((q * 2 + kb) * 8 + nt) * 32 + lane];
                    MMA16816(acc[nt], av[0], av[1], av[2], av[3], b.x, b.y);
                }
                MMA16816(accz, av[0], av[1], av[2], av[3], ONES16, ONES16);
            }
        }

        // reload adj words for next iteration (L2 latency hidden by occupancy)
        if (hh + 1 < NIT) {
            const size_t wi = (size_t)(wb0 + 2 * (hh + 1)) * N;
            c1a = g_adjT[wi + r1];        c2a = g_adjT[wi + r2];
            c1b = g_adjT[wi + N + r1];    c2b = g_adjT[wi + N + r2];
        }
    }

    if (tq == 0) {
        g_Zp[split * N + r1] = accz[0];
        g_Zp[split * N + r2] = accz[2];
    }

    float* p1 = g_part + ((size_t)split * N + r1) * 64;
    float* p2 = g_part + ((size_t)split * N + r2) * 64;
    #pragma unroll
    for (int nt = 0; nt < 8; nt++) {
        const int c = nt * 8 + 2 * tq;
        *reinterpret_cast<float2*>(p1 + c) = make_float2(acc[nt][0], acc[nt][1]);
        *reinterpret_cast<float2*>(p2 + c) = make_float2(acc[nt][2], acc[nt][3]);
    }
}

// ================= K5: combine splits, normalize, relu =================
__global__ __launch_bounds__(256) void final_kernel(float* __restrict__ out) {
    const int idx = blockIdx.x * 256 + threadIdx.x;   // 8192*16 float4s
    const int row = idx >> 4;
    const int c4 = idx & 15;
    float z = 0.f;
    #pragma unroll
    for (int sp = 0; sp < NSPLIT; sp++) z += g_Zp[sp * N + row];
    const float inv = 1.f / z;
    const size_t off = (size_t)row * 64 + c4 * 4;
    float4 s = *reinterpret_cast<const float4*>(g_part + off);
    #pragma unroll
    for (int sp = 1; sp < NSPLIT; sp++) {
        const float4 p = *reinterpret_cast<const float4*>(g_part + (size_t)sp * N * 64 + off);
        s.x += p.x; s.y += p.y; s.z += p.z; s.w += p.w;
    }
    *reinterpret_cast<float4*>(out + off) = make_float4(
        fmaxf(s.x * inv, 0.f), fmaxf(s.y * inv, 0.f),
        fmaxf(s.z * inv, 0.f), fmaxf(s.w * inv, 0.f));
}

// ================= launch =================
extern "C" void kernel_launch(void* const* d_in, const int* in_sizes, int n_in,
                              void* d_out, int out_size) {
    const float* h   = (const float*)d_in[0];
    const int*   adj = (const int*)d_in[1];
    const float* W   = (const float*)d_in[2];
    const float* a   = (const float*)d_in[3];
    float*       out = (float*)d_out;

    fused0_kernel<<<WH_BLOCKS + BP_BLOCKS, 256>>>(h, W, adj);
    s_kernel<<<N / 8, 256>>>(a);
    epack_kernel<<<N / 256, 256>>>();
    gat_mma<<<dim3(NSPLIT, N / TIROWS), 256>>>();
    final_kernel<<<(N * 16) / 256, 256>>>(out);
}

// round 14
// speedup vs baseline: 1.0199x; 1.0199x over previous
#include <cuda_runtime.h>
#include <cuda_fp16.h>
#include <math.h>
#include <stdint.h>

#define N      8192
#define INCH   256
#define OUTCH  64
#define NSPLIT 8
#define JSPAN  (N / NSPLIT)     // 1024
#define TIROWS 256
#define NIT    (JSPAN / 64)     // 16 iterations (64 j each)
#define ONES16 0x3C003C00u
#define STAGES 4

// ---------------- device scratch ----------------
__device__ float    g_Wh[N * OUTCH];
__device__ float    g_s1[N], g_s2[N];
__device__ unsigned g_m2u;                        // encoded float max (idempotent)
__device__ __align__(16) uint2 g_arh[N];          // per-row (A1 h2, Ah h2) broadcast
__device__ __align__(16) uint2 g_eph[N / 2];      // per j-pair (E1 h2, Eh h2)
__device__ unsigned g_adjT[(N / 32) * N];         // bit-packed adj [word][row]
// B fragment-pairs: [kbg][ntp 0..3][lane] x uint4(nt0.b0, nt0.b1, nt1.b0, nt1.b1)
__device__ __align__(16) uint4 g_Bfrag[(N / 16) * 4 * 32];
__device__ float    g_part[NSPLIT * N * OUTCH];
__device__ float    g_Zp[NSPLIT * N];

__device__ __forceinline__ unsigned fenc(float f) {
    unsigned u = __float_as_uint(f);
    return (u & 0x80000000u) ? ~u : (u | 0x80000000u);
}
__device__ __forceinline__ float fdec(unsigned k) {
    return __uint_as_float((k & 0x80000000u) ? (k ^ 0x80000000u) : ~k);
}
__device__ __forceinline__ uint32_t f16x2_pack(float lo, float hi) {
    uint32_t r;
    asm("cvt.rn.f16x2.f32 %0, %1, %2;" : "=r"(r) : "f"(hi), "f"(lo));
    return r;
}
__device__ __forceinline__ uint32_t hmul2(uint32_t a, uint32_t b) {
    uint32_t d;
    asm("mul.f16x2 %0, %1, %2;" : "=r"(d) : "r"(a), "r"(b));
    return d;
}
__device__ __forceinline__ uint32_t hmax2(uint32_t a, uint32_t b) {
    uint32_t d;
    asm("max.f16x2 %0, %1, %2;" : "=r"(d) : "r"(a), "r"(b));
    return d;
}
__device__ __forceinline__ uint32_t mk_mask2(unsigned aw, int jloc) {
    const uint32_t y = (aw >> jloc) & 3u;
    const uint32_t x = y * 0x4080u;
    uint32_t m;
    asm("prmt.b32 %0, %1, %2, 0x9988;" : "=r"(m) : "r"(x), "r"(0u));
    return m;
}
__device__ __forceinline__ uint32_t smem_u32(const void* p) {
    uint32_t a;
    asm("{ .reg .u64 t; cvta.to.shared.u64 t, %1; cvt.u32.u64 %0, t; }" : "=r"(a) : "l"(p));
    return a;
}

#define MMA16816(d, a0, a1, a2, a3, b0, b1)                                       \
    asm volatile("mma.sync.aligned.m16n8k16.row.col.f32.f16.f16.f32 "            \
        "{%0,%1,%2,%3}, {%4,%5,%6,%7}, {%8,%9}, {%0,%1,%2,%3};"                  \
        : "+f"((d)[0]), "+f"((d)[1]), "+f"((d)[2]), "+f"((d)[3])                  \
        : "r"(a0), "r"(a1), "r"(a2), "r"(a3), "r"(b0), "r"(b1))

#define CP16(dst, src) \
    asm volatile("cp.async.cg.shared.global [%0], [%1], 16;" :: "r"(dst), "l"(src) : "memory")
#define CP_COMMIT()   asm volatile("cp.async.commit_group;" ::: "memory")
#define CP_WAIT(nn)   asm volatile("cp.async.wait_group %0;" :: "n"(nn) : "memory")

// ================= K0: fused wh-GEMM (blocks 0..511) + adj bitpack (rest) ======
#define WH_BLOCKS   (N / 16)          // 512
#define BP_BLOCKS   (8 * (N / 8))     // 8192

__global__ __launch_bounds__(256) void fused0_kernel(const float* __restrict__ h,
                                                     const float* __restrict__ W,
                                                     const int* __restrict__ adj) {
    __shared__ __align__(16) char smraw[64 * 64 * 4];
    const int t = threadIdx.x;
    const int bid = blockIdx.x;

    if (bid < WH_BLOCKS) {
        float* Ws = reinterpret_cast<float*>(smraw);
        const int col = t & 63;
        const int rowgrp = t >> 6;
        const int i0 = bid * 16;

        float acc[4] = {0.f, 0.f, 0.f, 0.f};
        for (int kc = 0; kc < 4; kc++) {
            __syncthreads();
            float4* wsv = reinterpret_cast<float4*>(Ws);
            const float4* wgv = reinterpret_cast<const float4*>(W + kc * 64 * 64);
            #pragma unroll
            for (int q = 0; q < 4; q++) wsv[t + 256 * q] = wgv[t + 256 * q];
            __syncthreads();

            #pragma unroll 4
            for (int kk = 0; kk < 64; kk += 4) {
                const int k = kc * 64 + kk;
                const float w0 = Ws[(kk + 0) * 64 + col];
                const float w1 = Ws[(kk + 1) * 64 + col];
                const float w2 = Ws[(kk + 2) * 64 + col];
                const float w3 = Ws[(kk + 3) * 64 + col];
                #pragma unroll
                for (int rr = 0; rr < 4; rr++) {
                    const int rrow = i0 + rowgrp * 4 + rr;
                    const float4 hv = *reinterpret_cast<const float4*>(h + (size_t)rrow * INCH + k);
                    acc[rr] += hv.x * w0 + hv.y * w1 + hv.z * w2 + hv.w * w3;
                }
            }
        }
        #pragma unroll
        for (int rr = 0; rr < 4; rr++)
            g_Wh[(size_t)(i0 + rowgrp * 4 + rr) * OUTCH + col] = acc[rr];

        // B fragment-pair layout (single fp16), k = row index, n = col
        const int kbg = i0 >> 4;
        const int nt = col >> 3;
        const int g = col & 7;
        uint32_t* bf = reinterpret_cast<uint32_t*>(g_Bfrag);
        #pragma unroll
        for (int p = 0; p < 2; p++) {
            const int kp = rowgrp * 4 + 2 * p;
            const int slotbase = (kp < 8) ? 0 : 1;
            const int tq = (kp < 8) ? (kp >> 1) : ((kp - 8) >> 1);
            const int lane = g * 4 + tq;
            const uint32_t hw = f16x2_pack(acc[2 * p], acc[2 * p + 1]);
            bf[(((size_t)(kbg * 4 + (nt >> 1)) * 32 + lane) << 2) + ((nt & 1) << 1) + slotbase] = hw;
        }
    } else {
        unsigned* sw = reinterpret_cast<unsigned*>(smraw);   // [32 words][9]
        const int b = bid - WH_BLOCKS;
        const int bx = b & 7;
        const int ry = b >> 3;
        const int wi = t >> 5, lane = t & 31;
        const int r = ry * 8 + wi;
        const int* rowp = adj + (size_t)r * N + (size_t)bx * 1024;
        #pragma unroll
        for (int ww = 0; ww < 32; ww++) {
            const int v = rowp[ww * 32 + lane];
            const unsigned word = __ballot_sync(0xffffffffu, v != 0);
            if (lane == 0) sw[ww * 9 + wi] = word;
        }
        __syncthreads();
        const int word = t >> 3, row = t & 7;
        g_adjT[(size_t)(bx * 32 + word) * N + ry * 8 + row] = sw[word * 9 + row];
    }
}

// ================= K2: s1/s2 + encoded global max of s2 =================
__global__ __launch_bounds__(256) void s_kernel(const float* __restrict__ a) {
    __shared__ float sm2[8];
    const int wid = threadIdx.x >> 5;
    const int lane = threadIdx.x & 31;
    const int i = blockIdx.x * 8 + wid;
    const float v1 = g_Wh[(size_t)i * 64 + lane];
    const float v2 = g_Wh[(size_t)i * 64 + 32 + lane];
    float p1 = v1 * a[lane] + v2 * a[32 + lane];
    float p2 = v1 * a[64 + lane] + v2 * a[96 + lane];
    #pragma unroll
    for (int o = 16; o; o >>= 1) {
        p1 += __shfl_xor_sync(0xffffffffu, p1, o);
        p2 += __shfl_xor_sync(0xffffffffu, p2, o);
    }
    if (lane == 0) { g_s1[i] = p1; g_s2[i] = p2; sm2[wid] = p2; }
    __syncthreads();
    if (threadIdx.x == 0) {
        float m2 = sm2[0];
        #pragma unroll
        for (int q = 1; q < 8; q++) m2 = fmaxf(m2, sm2[q]);
        atomicMax(&g_m2u, fenc(m2));
    }
}

// ================= K3: per-node half2 factors (per-row normalized) =============
__global__ __launch_bounds__(256) void epack_kernel() {
    const int i = blockIdx.x * 256 + threadIdx.x;
    const float M2 = fdec(g_m2u);
    if (i < N) {
        const float X = g_s1[i] + M2;
        const float Lrow = (X >= 0.f) ? X : 0.5f * X;
        const float A1 = expf(X - Lrow);
        const float Ah = expf(0.5f * X - Lrow);
        g_arh[i] = make_uint2(f16x2_pack(A1, A1), f16x2_pack(Ah, Ah));
    }
    if (i < N / 2) {
        const float s2a = g_s2[2 * i] - M2, s2b = g_s2[2 * i + 1] - M2;
        g_eph[i] = make_uint2(f16x2_pack(expf(s2a), expf(s2b)),
                              f16x2_pack(expf(0.5f * s2a), expf(0.5f * s2b)));
    }
}

// ================= K4: M=32/warp, fp16 mma, uint4 B fragments =================
__global__ __launch_bounds__(256, 2) void gat_mma() {
    __shared__ __align__(16) uint4 smB[STAGES * 512];    // 4 x 8KB B buffers
    __shared__ __align__(16) uint2 smE[STAGES * 32];     // 4 x 256B ep buffers

    const int t = threadIdx.x;
    const int w = t >> 5, lane = t & 31;
    const int g = lane >> 2, tq = lane & 3;
    const int split = blockIdx.x;
    const int rowbase = blockIdx.y * TIROWS;
    const int jbase = split * JSPAN;
    const int kbg0 = jbase >> 4;
    const int wb0 = jbase >> 5;

    const int r1 = rowbase + w * 32 + g;       // set0: rows r1, r1+8
    const int r3 = r1 + 16;                    // set1: rows r3, r3+8
    const uint2 ar1 = g_arh[r1];
    const uint2 ar2 = g_arh[r1 + 8];
    const uint2 ar3 = g_arh[r3];
    const uint2 ar4 = g_arh[r3 + 8];

    float acc0[8][4], acc1[8][4];
    #pragma unroll
    for (int nt = 0; nt < 8; nt++)
        #pragma unroll
        for (int c = 0; c < 4; c++) { acc0[nt][c] = 0.f; acc1[nt][c] = 0.f; }
    float accz0[4] = {0.f, 0.f, 0.f, 0.f};
    float accz1[4] = {0.f, 0.f, 0.f, 0.f};

    // adjacency: 2 words (64 j) x 4 rows per iteration
    unsigned cw[2][4];
    {
        const size_t wi = (size_t)wb0 * N;
        cw[0][0] = g_adjT[wi + r1];     cw[0][1] = g_adjT[wi + r1 + 8];
        cw[0][2] = g_adjT[wi + r3];     cw[0][3] = g_adjT[wi + r3 + 8];
        cw[1][0] = g_adjT[wi + N + r1]; cw[1][1] = g_adjT[wi + N + r1 + 8];
        cw[1][2] = g_adjT[wi + N + r3]; cw[1][3] = g_adjT[wi + N + r3 + 8];
    }

    const uint4* bsrc4 = g_Bfrag + (size_t)kbg0 * 128;    // 512 uint4 per iter
    const uint4* esrc4 = reinterpret_cast<const uint4*>(g_eph + jbase / 2);
    const uint32_t sbB = smem_u32(smB);
    const uint32_t sbE = smem_u32(smE);

    #pragma unroll
    for (int s = 0; s < STAGES - 1; s++) {
        CP16(sbB + s * 8192 + t * 16, bsrc4 + (size_t)s * 512 + t);
        CP16(sbB + s * 8192 + 4096 + t * 16, bsrc4 + (size_t)s * 512 + 256 + t);
        if (t < 16) CP16(sbE + s * 256 + t * 16, esrc4 + s * 16 + t);
        CP_COMMIT();
    }

    for (int hh = 0; hh < NIT; hh++) {
        const int slot = hh % STAGES;
        CP_WAIT(2);
        __syncthreads();

        if (hh + STAGES - 1 < NIT) {
            const int hs = hh + STAGES - 1;
            const int ns = hs % STAGES;
            CP16(sbB + ns * 8192 + t * 16, bsrc4 + (size_t)hs * 512 + t);
            CP16(sbB + ns * 8192 + 4096 + t * 16, bsrc4 + (size_t)hs * 512 + 256 + t);
            if (t < 16) CP16(sbE + ns * 256 + t * 16, esrc4 + hs * 16 + t);
        }
        CP_COMMIT();

        const uint4* bs = smB + slot * 512;
        const uint2* es = smE + slot * 32;

        #pragma unroll
        for (int q = 0; q < 2; q++) {
            #pragma unroll
            for (int kb = 0; kb < 2; kb++) {
                const int kt = q * 2 + kb;
                uint32_t av0[4], av1[4];
                #pragma unroll
                for (int pr = 0; pr < 2; pr++) {
                    const int jloc = kb * 16 + pr * 8 + 2 * tq;
                    const uint2 e = es[kt * 8 + pr * 4 + tq];
                    const uint32_t e1h = hmul2(ar1.x, e.x), e1l = hmul2(ar1.y, e.y);
                    const uint32_t e2h = hmul2(ar2.x, e.x), e2l = hmul2(ar2.y, e.y);
                    const uint32_t e3h = hmul2(ar3.x, e.x), e3l = hmul2(ar3.y, e.y);
                    const uint32_t e4h = hmul2(ar4.x, e.x), e4l = hmul2(ar4.y, e.y);
                    av0[2 * pr + 0] = hmax2(e1h, e1l) & mk_mask2(cw[q][0], jloc);
                    av0[2 * pr + 1] = hmax2(e2h, e2l) & mk_mask2(cw[q][1], jloc);
                    av1[2 * pr + 0] = hmax2(e3h, e3l) & mk_mask2(cw[q][2], jloc);
                    av1[2 * pr + 1] = hmax2(e4h, e4l) & mk_mask2(cw[q][3], jloc);
                }
                #pragma unroll
                for (int ntp = 0; ntp < 4; ntp++) {
                    const uint4 b = bs[(kt * 4 + ntp) * 32 + lane];
                    MMA16816(acc0[2 * ntp + 0], av0[0], av0[1], av0[2], av0[3], b.x, b.y);
                    MMA16816(acc0[2 * ntp + 1], av0[0], av0[1], av0[2], av0[3], b.z, b.w);
                    MMA16816(acc1[2 * ntp + 0], av1[0], av1[1], av1[2], av1[3], b.x, b.y);
                    MMA16816(acc1[2 * ntp + 1], av1[0], av1[1], av1[2], av1[3], b.z, b.w);
                }
                MMA16816(accz0, av0[0], av0[1], av0[2], av0[3], ONES16, ONES16);
                MMA16816(accz1, av1[0], av1[1], av1[2], av1[3], ONES16, ONES16);
            }
        }

        // reload adjacency for next iteration
        if (hh + 1 < NIT) {
            const size_t wi = (size_t)(wb0 + 2 * (hh + 1)) * N;
            cw[0][0] = g_adjT[wi + r1];     cw[0][1] = g_adjT[wi + r1 + 8];
            cw[0][2] = g_adjT[wi + r3];     cw[0][3] = g_adjT[wi + r3 + 8];
            cw[1][0] = g_adjT[wi + N + r1]; cw[1][1] = g_adjT[wi + N + r1 + 8];
            cw[1][2] = g_adjT[wi + N + r3]; cw[1][3] = g_adjT[wi + N + r3 + 8];
        }
    }

    if (tq == 0) {
        g_Zp[split * N + r1]     = accz0[0];
        g_Zp[split * N + r1 + 8] = accz0[2];
        g_Zp[split * N + r3]     = accz1[0];
        g_Zp[split * N + r3 + 8] = accz1[2];
    }

    float* p1 = g_part + ((size_t)split * N + r1) * 64;
    float* p2 = g_part + ((size_t)split * N + r1 + 8) * 64;
    float* p3 = g_part + ((size_t)split * N + r3) * 64;
    float* p4 = g_part + ((size_t)split * N + r3 + 8) * 64;
    #pragma unroll
    for (int nt = 0; nt < 8; nt++) {
        const int c = nt * 8 + 2 * tq;
        *reinterpret_cast<float2*>(p1 + c) = make_float2(acc0[nt][0], acc0[nt][1]);
        *reinterpret_cast<float2*>(p2 + c) = make_float2(acc0[nt][2], acc0[nt][3]);
        *reinterpret_cast<float2*>(p3 + c) = make_float2(acc1[nt][0], acc1[nt][1]);
        *reinterpret_cast<float2*>(p4 + c) = make_float2(acc1[nt][2], acc1[nt][3]);
    }
}

// ================= K5: combine splits, normalize, relu =================
__global__ __launch_bounds__(256) void final_kernel(float* __restrict__ out) {
    const int idx = blockIdx.x * 256 + threadIdx.x;   // 8192*16 float4s
    const int row = idx >> 4;
    const int c4 = idx & 15;
    float z = 0.f;
    #pragma unroll
    for (int sp = 0; sp < NSPLIT; sp++) z += g_Zp[sp * N + row];
    const float inv = 1.f / z;
    const size_t off = (size_t)row * 64 + c4 * 4;
    float4 s = *reinterpret_cast<const float4*>(g_part + off);
    #pragma unroll
    for (int sp = 1; sp < NSPLIT; sp++) {
        const float4 p = *reinterpret_cast<const float4*>(g_part + (size_t)sp * N * 64 + off);
        s.x += p.x; s.y += p.y; s.z += p.z; s.w += p.w;
    }
    *reinterpret_cast<float4*>(out + off) = make_float4(
        fmaxf(s.x * inv, 0.f), fmaxf(s.y * inv, 0.f),
        fmaxf(s.z * inv, 0.f), fmaxf(s.w * inv, 0.f));
}

// ================= launch =================
extern "C" void kernel_launch(void* const* d_in, const int* in_sizes, int n_in,
                              void* d_out, int out_size) {
    const float* h   = (const float*)d_in[0];
    const int*   adj = (const int*)d_in[1];
    const float* W   = (const float*)d_in[2];
    const float* a   = (const float*)d_in[3];
    float*       out = (float*)d_out;

    fused0_kernel<<<WH_BLOCKS + BP_BLOCKS, 256>>>(h, W, adj);
    s_kernel<<<N / 8, 256>>>(a);
    epack_kernel<<<N / 256, 256>>>();
    gat_mma<<<dim3(NSPLIT, N / TIROWS), 256>>>();
    final_kernel<<<(N * 16) / 256, 256>>>(out);
}

// round 15
// speedup vs baseline: 1.0956x; 1.0742x over previous
#include <cuda_runtime.h>
#include <cuda_fp16.h>
#include <math.h>
#include <stdint.h>

#define N      8192
#define INCH   256
#define OUTCH  64
#define NSPLIT 8
#define JSPAN  (N / NSPLIT)     // 1024
#define TIROWS 256
#define NIT    (JSPAN / 64)     // 16 iterations (64 j each)
#define ONES16 0x3C003C00u
#define STAGES 4

// ---------------- device scratch ----------------
__device__ float    g_Wh[N * OUTCH];
__device__ float    g_s1[N], g_s2[N];
__device__ unsigned g_m2u;                        // encoded float max (idempotent)
__device__ __align__(16) uint2 g_arh[N];          // per-row (A1 h2, Ah h2) broadcast
__device__ __align__(16) uint2 g_eph[N / 2];      // per j-pair (E1 h2, Eh h2)
__device__ __align__(16) unsigned g_adjT[(N / 32) * N];  // bit-packed adj [word][row]
// B fragment-pairs: [kbg][ntp 0..3][lane] x uint4(nt0.b0, nt0.b1, nt1.b0, nt1.b1)
__device__ __align__(16) uint4 g_Bfrag[(N / 16) * 4 * 32];
__device__ float    g_part[NSPLIT * N * OUTCH];
__device__ float    g_Zp[NSPLIT * N];

__device__ __forceinline__ unsigned fenc(float f) {
    unsigned u = __float_as_uint(f);
    return (u & 0x80000000u) ? ~u : (u | 0x80000000u);
}
__device__ __forceinline__ float fdec(unsigned k) {
    return __uint_as_float((k & 0x80000000u) ? (k ^ 0x80000000u) : ~k);
}
__device__ __forceinline__ uint32_t f16x2_pack(float lo, float hi) {
    uint32_t r;
    asm("cvt.rn.f16x2.f32 %0, %1, %2;" : "=r"(r) : "f"(hi), "f"(lo));
    return r;
}
__device__ __forceinline__ uint32_t hmul2(uint32_t a, uint32_t b) {
    uint32_t d;
    asm("mul.f16x2 %0, %1, %2;" : "=r"(d) : "r"(a), "r"(b));
    return d;
}
__device__ __forceinline__ uint32_t hmax2(uint32_t a, uint32_t b) {
    uint32_t d;
    asm("max.f16x2 %0, %1, %2;" : "=r"(d) : "r"(a), "r"(b));
    return d;
}
__device__ __forceinline__ uint32_t mk_mask2(unsigned aw, int jloc) {
    const uint32_t y = (aw >> jloc) & 3u;
    const uint32_t x = y * 0x4080u;
    uint32_t m;
    asm("prmt.b32 %0, %1, %2, 0x9988;" : "=r"(m) : "r"(x), "r"(0u));
    return m;
}
__device__ __forceinline__ uint32_t smem_u32(const void* p) {
    uint32_t a;
    asm("{ .reg .u64 t; cvta.to.shared.u64 t, %1; cvt.u32.u64 %0, t; }" : "=r"(a) : "l"(p));
    return a;
}

#define MMA16816(d, a0, a1, a2, a3, b0, b1)                                       \
    asm volatile("mma.sync.aligned.m16n8k16.row.col.f32.f16.f16.f32 "            \
        "{%0,%1,%2,%3}, {%4,%5,%6,%7}, {%8,%9}, {%0,%1,%2,%3};"                  \
        : "+f"((d)[0]), "+f"((d)[1]), "+f"((d)[2]), "+f"((d)[3])                  \
        : "r"(a0), "r"(a1), "r"(a2), "r"(a3), "r"(b0), "r"(b1))

#define CP16(dst, src) \
    asm volatile("cp.async.cg.shared.global [%0], [%1], 16;" :: "r"(dst), "l"(src) : "memory")
#define CP_COMMIT()   asm volatile("cp.async.commit_group;" ::: "memory")
#define CP_WAIT(nn)   asm volatile("cp.async.wait_group %0;" :: "n"(nn) : "memory")

// ================= K0: fused wh-GEMM (blocks 0..511) + adj bitpack (rest) ======
#define WH_BLOCKS   (N / 16)          // 512
#define BP_BLOCKS   (8 * (N / 8))     // 8192
#define NIBP        264               // nibble array pitch (uint32), pads banks

__global__ __launch_bounds__(256) void fused0_kernel(const float* __restrict__ h,
                                                     const float* __restrict__ W,
                                                     const int* __restrict__ adj) {
    __shared__ __align__(16) char smraw[64 * 64 * 4];
    const int t = threadIdx.x;
    const int bid = blockIdx.x;

    if (bid < WH_BLOCKS) {
        float* Ws = reinterpret_cast<float*>(smraw);
        const int col = t & 63;
        const int rowgrp = t >> 6;
        const int i0 = bid * 16;

        float acc[4] = {0.f, 0.f, 0.f, 0.f};
        for (int kc = 0; kc < 4; kc++) {
            __syncthreads();
            float4* wsv = reinterpret_cast<float4*>(Ws);
            const float4* wgv = reinterpret_cast<const float4*>(W + kc * 64 * 64);
            #pragma unroll
            for (int q = 0; q < 4; q++) wsv[t + 256 * q] = wgv[t + 256 * q];
            __syncthreads();

            #pragma unroll 4
            for (int kk = 0; kk < 64; kk += 4) {
                const int k = kc * 64 + kk;
                const float w0 = Ws[(kk + 0) * 64 + col];
                const float w1 = Ws[(kk + 1) * 64 + col];
                const float w2 = Ws[(kk + 2) * 64 + col];
                const float w3 = Ws[(kk + 3) * 64 + col];
                #pragma unroll
                for (int rr = 0; rr < 4; rr++) {
                    const int rrow = i0 + rowgrp * 4 + rr;
                    const float4 hv = *reinterpret_cast<const float4*>(h + (size_t)rrow * INCH + k);
                    acc[rr] += hv.x * w0 + hv.y * w1 + hv.z * w2 + hv.w * w3;
                }
            }
        }
        #pragma unroll
        for (int rr = 0; rr < 4; rr++)
            g_Wh[(size_t)(i0 + rowgrp * 4 + rr) * OUTCH + col] = acc[rr];

        // B fragment-pair layout (single fp16), k = row index, n = col
        const int kbg = i0 >> 4;
        const int nt = col >> 3;
        const int g = col & 7;
        uint32_t* bf = reinterpret_cast<uint32_t*>(g_Bfrag);
        #pragma unroll
        for (int p = 0; p < 2; p++) {
            const int kp = rowgrp * 4 + 2 * p;
            const int slotbase = (kp < 8) ? 0 : 1;
            const int tq = (kp < 8) ? (kp >> 1) : ((kp - 8) >> 1);
            const int lane = g * 4 + tq;
            const uint32_t hw = f16x2_pack(acc[2 * p], acc[2 * p + 1]);
            bf[(((size_t)(kbg * 4 + (nt >> 1)) * 32 + lane) << 2) + ((nt & 1) << 1) + slotbase] = hw;
        }
    } else {
        // ---- bitpack: 8 rows x 1024 j, int4 loads + nibble assembly ----
        unsigned* nib = reinterpret_cast<unsigned*>(smraw);   // [8][NIBP]
        const int b = bid - WH_BLOCKS;
        const int bx = b & 7;              // j chunk of 1024
        const int ry = b >> 3;             // row group of 8
        const int wi = t >> 5, lane = t & 31;
        const int r = ry * 8 + wi;
        const int4* rowp = reinterpret_cast<const int4*>(adj + (size_t)r * N + (size_t)bx * 1024);
        #pragma unroll
        for (int rd = 0; rd < 8; rd++) {
            const int4 v = rowp[rd * 32 + lane];
            unsigned nb = (v.x != 0) ? 1u : 0u;
            nb |= (v.y != 0) ? 2u : 0u;
            nb |= (v.z != 0) ? 4u : 0u;
            nb |= (v.w != 0) ? 8u : 0u;
            nib[wi * NIBP + rd * 32 + lane] = nb;
        }
        __syncthreads();
        // assemble: thread t -> word (t>>3), row (t&7)
        const int word = t >> 3, row = t & 7;
        const uint4 nA = *reinterpret_cast<const uint4*>(nib + row * NIBP + word * 8);
        const uint4 nB = *reinterpret_cast<const uint4*>(nib + row * NIBP + word * 8 + 4);
        unsigned wv = nA.x | (nA.y << 4) | (nA.z << 8) | (nA.w << 12)
                    | (nB.x << 16) | (nB.y << 20) | (nB.z << 24) | (nB.w << 28);
        g_adjT[(size_t)(bx * 32 + word) * N + ry * 8 + row] = wv;
    }
}

// ================= K2: s1/s2 + encoded global max of s2 =================
__global__ __launch_bounds__(256) void s_kernel(const float* __restrict__ a) {
    __shared__ float sm2[8];
    const int wid = threadIdx.x >> 5;
    const int lane = threadIdx.x & 31;
    const int i = blockIdx.x * 8 + wid;
    const float v1 = g_Wh[(size_t)i * 64 + lane];
    const float v2 = g_Wh[(size_t)i * 64 + 32 + lane];
    float p1 = v1 * a[lane] + v2 * a[32 + lane];
    float p2 = v1 * a[64 + lane] + v2 * a[96 + lane];
    #pragma unroll
    for (int o = 16; o; o >>= 1) {
        p1 += __shfl_xor_sync(0xffffffffu, p1, o);
        p2 += __shfl_xor_sync(0xffffffffu, p2, o);
    }
    if (lane == 0) { g_s1[i] = p1; g_s2[i] = p2; sm2[wid] = p2; }
    __syncthreads();
    if (threadIdx.x == 0) {
        float m2 = sm2[0];
        #pragma unroll
        for (int q = 1; q < 8; q++) m2 = fmaxf(m2, sm2[q]);
        atomicMax(&g_m2u, fenc(m2));
    }
}

// ================= K3: per-node half2 factors (per-row normalized) =============
__global__ __launch_bounds__(256) void epack_kernel() {
    const int i = blockIdx.x * 256 + threadIdx.x;
    const float M2 = fdec(g_m2u);
    if (i < N) {
        const float X = g_s1[i] + M2;
        const float Lrow = (X >= 0.f) ? X : 0.5f * X;
        const float A1 = expf(X - Lrow);
        const float Ah = expf(0.5f * X - Lrow);
        g_arh[i] = make_uint2(f16x2_pack(A1, A1), f16x2_pack(Ah, Ah));
    }
    if (i < N / 2) {
        const float s2a = g_s2[2 * i] - M2, s2b = g_s2[2 * i + 1] - M2;
        g_eph[i] = make_uint2(f16x2_pack(expf(s2a), expf(s2b)),
                              f16x2_pack(expf(0.5f * s2a), expf(0.5f * s2b)));
    }
}

// ================= K4: M=32/warp fp16 mma; B+ep+adj all cp.async staged ========
__global__ __launch_bounds__(256, 2) void gat_mma() {
    __shared__ __align__(16) uint4    smB[STAGES * 512];   // 4 x 8KB B
    __shared__ __align__(16) uint2    smE[STAGES * 32];    // 4 x 256B ep
    __shared__ __align__(16) unsigned smA[STAGES * 512];   // 4 x 2KB adj words

    const int t = threadIdx.x;
    const int w = t >> 5, lane = t & 31;
    const int g = lane >> 2, tq = lane & 3;
    const int split = blockIdx.x;
    const int rowbase = blockIdx.y * TIROWS;
    const int jbase = split * JSPAN;
    const int kbg0 = jbase >> 4;
    const int wb0 = jbase >> 5;

    const int r1 = rowbase + w * 32 + g;       // set0: rows r1, r1+8
    const int r3 = r1 + 16;                    // set1: rows r3, r3+8
    const int rl = w * 32 + g;                 // local row of r1
    const uint2 ar1 = g_arh[r1];
    const uint2 ar2 = g_arh[r1 + 8];
    const uint2 ar3 = g_arh[r3];
    const uint2 ar4 = g_arh[r3 + 8];

    float acc0[8][4], acc1[8][4];
    #pragma unroll
    for (int nt = 0; nt < 8; nt++)
        #pragma unroll
        for (int c = 0; c < 4; c++) { acc0[nt][c] = 0.f; acc1[nt][c] = 0.f; }
    float accz0[4] = {0.f, 0.f, 0.f, 0.f};
    float accz1[4] = {0.f, 0.f, 0.f, 0.f};

    const uint4* bsrc4 = g_Bfrag + (size_t)kbg0 * 128;
    const uint4* esrc4 = reinterpret_cast<const uint4*>(g_eph + jbase / 2);
    const uint32_t sbB = smem_u32(smB);
    const uint32_t sbE = smem_u32(smE);
    const uint32_t sbA = smem_u32(smA);

    // adj cp.async source: per stage s, words wb0+2s, wb0+2s+1, rows [rowbase,+256)
    const int aq = t >> 6;              // 0/1 (threads 0..127 active)
    const int arr = (t & 63) * 4;

    #pragma unroll
    for (int s = 0; s < STAGES - 1; s++) {
        CP16(sbB + s * 8192 + t * 16, bsrc4 + (size_t)s * 512 + t);
        CP16(sbB + s * 8192 + 4096 + t * 16, bsrc4 + (size_t)s * 512 + 256 + t);
        if (t < 16) CP16(sbE + s * 256 + t * 16, esrc4 + s * 16 + t);
        if (t < 128)
            CP16(sbA + s * 2048 + aq * 1024 + arr * 4,
                 g_adjT + (size_t)(wb0 + 2 * s + aq) * N + rowbase + arr);
        CP_COMMIT();
    }

    for (int hh = 0; hh < NIT; hh++) {
        const int slot = hh % STAGES;
        CP_WAIT(2);
        __syncthreads();

        if (hh + STAGES - 1 < NIT) {
            const int hs = hh + STAGES - 1;
            const int ns = hs % STAGES;
            CP16(sbB + ns * 8192 + t * 16, bsrc4 + (size_t)hs * 512 + t);
            CP16(sbB + ns * 8192 + 4096 + t * 16, bsrc4 + (size_t)hs * 512 + 256 + t);
            if (t < 16) CP16(sbE + ns * 256 + t * 16, esrc4 + hs * 16 + t);
            if (t < 128)
                CP16(sbA + ns * 2048 + aq * 1024 + arr * 4,
                     g_adjT + (size_t)(wb0 + 2 * hs + aq) * N + rowbase + arr);
        }
        CP_COMMIT();

        const uint4* bs = smB + slot * 512;
        const uint2* es = smE + slot * 32;
        const unsigned* as = smA + slot * 512;

        unsigned cw[2][4];
        #pragma unroll
        for (int q = 0; q < 2; q++) {
            cw[q][0] = as[q * 256 + rl];
            cw[q][1] = as[q * 256 + rl + 8];
            cw[q][2] = as[q * 256 + rl + 16];
            cw[q][3] = as[q * 256 + rl + 24];
        }

        #pragma unroll
        for (int q = 0; q < 2; q++) {
            #pragma unroll
            for (int kb = 0; kb < 2; kb++) {
                const int kt = q * 2 + kb;
                uint32_t av0[4], av1[4];
                #pragma unroll
                for (int pr = 0; pr < 2; pr++) {
                    const int jloc = kb * 16 + pr * 8 + 2 * tq;
                    const uint2 e = es[kt * 8 + pr * 4 + tq];
                    const uint32_t e1h = hmul2(ar1.x, e.x), e1l = hmul2(ar1.y, e.y);
                    const uint32_t e2h = hmul2(ar2.x, e.x), e2l = hmul2(ar2.y, e.y);
                    const uint32_t e3h = hmul2(ar3.x, e.x), e3l = hmul2(ar3.y, e.y);
                    const uint32_t e4h = hmul2(ar4.x, e.x), e4l = hmul2(ar4.y, e.y);
                    av0[2 * pr + 0] = hmax2(e1h, e1l) & mk_mask2(cw[q][0], jloc);
                    av0[2 * pr + 1] = hmax2(e2h, e2l) & mk_mask2(cw[q][1], jloc);
                    av1[2 * pr + 0] = hmax2(e3h, e3l) & mk_mask2(cw[q][2], jloc);
                    av1[2 * pr + 1] = hmax2(e4h, e4l) & mk_mask2(cw[q][3], jloc);
                }
                #pragma unroll
                for (int ntp = 0; ntp < 4; ntp++) {
                    const uint4 b = bs[(kt * 4 + ntp) * 32 + lane];
                    MMA16816(acc0[2 * ntp + 0], av0[0], av0[1], av0[2], av0[3], b.x, b.y);
                    MMA16816(acc0[2 * ntp + 1], av0[0], av0[1], av0[2], av0[3], b.z, b.w);
                    MMA16816(acc1[2 * ntp + 0], av1[0], av1[1], av1[2], av1[3], b.x, b.y);
                    MMA16816(acc1[2 * ntp + 1], av1[0], av1[1], av1[2], av1[3], b.z, b.w);
                }
                MMA16816(accz0, av0[0], av0[1], av0[2], av0[3], ONES16, ONES16);
                MMA16816(accz1, av1[0], av1[1], av1[2], av1[3], ONES16, ONES16);
            }
        }
    }

    if (tq == 0) {
        g_Zp[split * N + r1]     = accz0[0];
        g_Zp[split * N + r1 + 8] = accz0[2];
        g_Zp[split * N + r3]     = accz1[0];
        g_Zp[split * N + r3 + 8] = accz1[2];
    }

    float* p1 = g_part + ((size_t)split * N + r1) * 64;
    float* p2 = g_part + ((size_t)split * N + r1 + 8) * 64;
    float* p3 = g_part + ((size_t)split * N + r3) * 64;
    float* p4 = g_part + ((size_t)split * N + r3 + 8) * 64;
    #pragma unroll
    for (int nt = 0; nt < 8; nt++) {
        const int c = nt * 8 + 2 * tq;
        *reinterpret_cast<float2*>(p1 + c) = make_float2(acc0[nt][0], acc0[nt][1]);
        *reinterpret_cast<float2*>(p2 + c) = make_float2(acc0[nt][2], acc0[nt][3]);
        *reinterpret_cast<float2*>(p3 + c) = make_float2(acc1[nt][0], acc1[nt][1]);
        *reinterpret_cast<float2*>(p4 + c) = make_float2(acc1[nt][2], acc1[nt][3]);
    }
}

// ================= K5: combine splits, normalize, relu =================
__global__ __launch_bounds__(256) void final_kernel(float* __restrict__ out) {
    const int idx = blockIdx.x * 256 + threadIdx.x;   // 8192*16 float4s
    const int row = idx >> 4;
    const int c4 = idx & 15;
    float z = 0.f;
    #pragma unroll
    for (int sp = 0; sp < NSPLIT; sp++) z += g_Zp[sp * N + row];
    const float inv = 1.f / z;
    const size_t off = (size_t)row * 64 + c4 * 4;
    float4 s = *reinterpret_cast<const float4*>(g_part + off);
    #pragma unroll
    for (int sp = 1; sp < NSPLIT; sp++) {
        const float4 p = *reinterpret_cast<const float4*>(g_part + (size_t)sp * N * 64 + off);
        s.x += p.x; s.y += p.y; s.z += p.z; s.w += p.w;
    }
    *reinterpret_cast<float4*>(out + off) = make_float4(
        fmaxf(s.x * inv, 0.f), fmaxf(s.y * inv, 0.f),
        fmaxf(s.z * inv, 0.f), fmaxf(s.w * inv, 0.f));
}

// ================= launch =================
extern "C" void kernel_launch(void* const* d_in, const int* in_sizes, int n_in,
                              void* d_out, int out_size) {
    const float* h   = (const float*)d_in[0];
    const int*   adj = (const int*)d_in[1];
    const float* W   = (const float*)d_in[2];
    const float* a   = (const float*)d_in[3];
    float*       out = (float*)d_out;

    fused0_kernel<<<WH_BLOCKS + BP_BLOCKS, 256>>>(h, W, adj);
    s_kernel<<<N / 8, 256>>>(a);
    epack_kernel<<<N / 256, 256>>>();
    gat_mma<<<dim3(NSPLIT, N / TIROWS), 256>>>();
    final_kernel<<<(N * 16) / 256, 256>>>(out);
}

// round 16
// speedup vs baseline: 1.1582x; 1.0572x over previous
#include <cuda_runtime.h>
#include <cuda_fp16.h>
#include <math.h>
#include <stdint.h>

#define N      8192
#define INCH   256
#define OUTCH  64
#define NSPLIT 8
#define JSPAN  (N / NSPLIT)     // 1024
#define TIROWS 256
#define NIT    (JSPAN / 64)     // 16 iterations (64 j each)
#define ONES16 0x3C003C00u
#define STAGES 4

// ---------------- device scratch ----------------
__device__ float    g_Wh[N * OUTCH];
__device__ float    g_s1[N], g_s2[N];
__device__ unsigned g_m2u;                        // encoded float max (idempotent)
__device__ __align__(16) unsigned g_adjT[(N / 32) * N];  // bit-packed adj [word][row]
// B fragment-pairs: [kbg][ntp 0..3][lane] x uint4(nt0.b0, nt0.b1, nt1.b0, nt1.b1)
__device__ __align__(16) uint4 g_Bfrag[(N / 16) * 4 * 32];
__device__ float    g_part[NSPLIT * N * OUTCH];
__device__ float    g_Zp[NSPLIT * N];

__device__ __forceinline__ unsigned fenc(float f) {
    unsigned u = __float_as_uint(f);
    return (u & 0x80000000u) ? ~u : (u | 0x80000000u);
}
__device__ __forceinline__ float fdec(unsigned k) {
    return __uint_as_float((k & 0x80000000u) ? (k ^ 0x80000000u) : ~k);
}
__device__ __forceinline__ uint32_t f16x2_pack(float lo, float hi) {
    uint32_t r;
    asm("cvt.rn.f16x2.f32 %0, %1, %2;" : "=r"(r) : "f"(hi), "f"(lo));
    return r;
}
__device__ __forceinline__ uint32_t hmul2(uint32_t a, uint32_t b) {
    uint32_t d;
    asm("mul.f16x2 %0, %1, %2;" : "=r"(d) : "r"(a), "r"(b));
    return d;
}
__device__ __forceinline__ uint32_t hmax2(uint32_t a, uint32_t b) {
    uint32_t d;
    asm("max.f16x2 %0, %1, %2;" : "=r"(d) : "r"(a), "r"(b));
    return d;
}
__device__ __forceinline__ uint32_t mk_mask2(unsigned aw, int jloc) {
    const uint32_t y = (aw >> jloc) & 3u;
    const uint32_t x = y * 0x4080u;
    uint32_t m;
    asm("prmt.b32 %0, %1, %2, 0x9988;" : "=r"(m) : "r"(x), "r"(0u));
    return m;
}
__device__ __forceinline__ uint32_t smem_u32(const void* p) {
    uint32_t a;
    asm("{ .reg .u64 t; cvta.to.shared.u64 t, %1; cvt.u32.u64 %0, t; }" : "=r"(a) : "l"(p));
    return a;
}
// per-row ar factors: X = s1 + M2; Lrow = lrelu(X); (A1, Ah) broadcast half2
__device__ __forceinline__ uint2 mk_ar(float s1v, float M2) {
    const float X = s1v + M2;
    const float Lrow = (X >= 0.f) ? X : 0.5f * X;
    const float A1 = expf(X - Lrow);
    const float Ah = expf(0.5f * X - Lrow);
    return make_uint2(f16x2_pack(A1, A1), f16x2_pack(Ah, Ah));
}

#define MMA16816(d, a0, a1, a2, a3, b0, b1)                                       \
    asm volatile("mma.sync.aligned.m16n8k16.row.col.f32.f16.f16.f32 "            \
        "{%0,%1,%2,%3}, {%4,%5,%6,%7}, {%8,%9}, {%0,%1,%2,%3};"                  \
        : "+f"((d)[0]), "+f"((d)[1]), "+f"((d)[2]), "+f"((d)[3])                  \
        : "r"(a0), "r"(a1), "r"(a2), "r"(a3), "r"(b0), "r"(b1))

#define CP16(dst, src) \
    asm volatile("cp.async.cg.shared.global [%0], [%1], 16;" :: "r"(dst), "l"(src) : "memory")
#define CP_COMMIT()   asm volatile("cp.async.commit_group;" ::: "memory")
#define CP_WAIT(nn)   asm volatile("cp.async.wait_group %0;" :: "n"(nn) : "memory")

// ================= K0: fused wh-GEMM + s1/s2/max (blocks 0..511) + bitpack =====
#define WH_BLOCKS   (N / 16)          // 512
#define BP_BLOCKS   (8 * (N / 8))     // 8192
#define NIBP        264               // nibble array pitch (uint32)

__global__ __launch_bounds__(256) void fused0_kernel(const float* __restrict__ h,
                                                     const float* __restrict__ W,
                                                     const float* __restrict__ a,
                                                     const int* __restrict__ adj) {
    __shared__ __align__(16) char smraw[64 * 64 * 4];
    const int t = threadIdx.x;
    const int bid = blockIdx.x;

    if (bid < WH_BLOCKS) {
        float* Ws = reinterpret_cast<float*>(smraw);
        const int col = t & 63;
        const int rowgrp = t >> 6;
        const int i0 = bid * 16;

        float acc[4] = {0.f, 0.f, 0.f, 0.f};
        for (int kc = 0; kc < 4; kc++) {
            __syncthreads();
            float4* wsv = reinterpret_cast<float4*>(Ws);
            const float4* wgv = reinterpret_cast<const float4*>(W + kc * 64 * 64);
            #pragma unroll
            for (int q = 0; q < 4; q++) wsv[t + 256 * q] = wgv[t + 256 * q];
            __syncthreads();

            #pragma unroll 4
            for (int kk = 0; kk < 64; kk += 4) {
                const int k = kc * 64 + kk;
                const float w0 = Ws[(kk + 0) * 64 + col];
                const float w1 = Ws[(kk + 1) * 64 + col];
                const float w2 = Ws[(kk + 2) * 64 + col];
                const float w3 = Ws[(kk + 3) * 64 + col];
                #pragma unroll
                for (int rr = 0; rr < 4; rr++) {
                    const int rrow = i0 + rowgrp * 4 + rr;
                    const float4 hv = *reinterpret_cast<const float4*>(h + (size_t)rrow * INCH + k);
                    acc[rr] += hv.x * w0 + hv.y * w1 + hv.z * w2 + hv.w * w3;
                }
            }
        }
        #pragma unroll
        for (int rr = 0; rr < 4; rr++)
            g_Wh[(size_t)(i0 + rowgrp * 4 + rr) * OUTCH + col] = acc[rr];

        // B fragment-pair layout (single fp16), k = row index, n = col
        const int kbg = i0 >> 4;
        const int nt = col >> 3;
        const int g = col & 7;
        uint32_t* bf = reinterpret_cast<uint32_t*>(g_Bfrag);
        #pragma unroll
        for (int p = 0; p < 2; p++) {
            const int kp = rowgrp * 4 + 2 * p;
            const int slotbase = (kp < 8) ? 0 : 1;
            const int tq = (kp < 8) ? (kp >> 1) : ((kp - 8) >> 1);
            const int lane = g * 4 + tq;
            const uint32_t hw = f16x2_pack(acc[2 * p], acc[2 * p + 1]);
            bf[(((size_t)(kbg * 4 + (nt >> 1)) * 32 + lane) << 2) + ((nt & 1) << 1) + slotbase] = hw;
        }

        // ---- fused s1/s2: reduce acc*a over the 64 cols (2 warps per rowgrp) ----
        const float a1c = a[col], a2c = a[64 + col];
        float p1[4], p2[4];
        #pragma unroll
        for (int rr = 0; rr < 4; rr++) { p1[rr] = acc[rr] * a1c; p2[rr] = acc[rr] * a2c; }
        #pragma unroll
        for (int o = 16; o; o >>= 1) {
            #pragma unroll
            for (int rr = 0; rr < 4; rr++) {
                p1[rr] += __shfl_xor_sync(0xffffffffu, p1[rr], o);
                p2[rr] += __shfl_xor_sync(0xffffffffu, p2[rr], o);
            }
        }
        __syncthreads();                       // Ws reuse
        float* sred = reinterpret_cast<float*>(smraw);   // [8 warps][8]
        const int wwid = t >> 5;
        if ((t & 31) == 0) {
            #pragma unroll
            for (int rr = 0; rr < 4; rr++) {
                sred[wwid * 8 + rr] = p1[rr];
                sred[wwid * 8 + 4 + rr] = p2[rr];
            }
        }
        __syncthreads();
        if (t < 16) {
            const int rg = t >> 2, rr = t & 3;
            const float v1 = sred[(2 * rg) * 8 + rr] + sred[(2 * rg + 1) * 8 + rr];
            const float v2 = sred[(2 * rg) * 8 + 4 + rr] + sred[(2 * rg + 1) * 8 + 4 + rr];
            g_s1[i0 + rg * 4 + rr] = v1;
            g_s2[i0 + rg * 4 + rr] = v2;
            atomicMax(&g_m2u, fenc(v2));
        }
    } else {
        // ---- bitpack: 8 rows x 1024 j, int4 loads + nibble assembly ----
        unsigned* nib = reinterpret_cast<unsigned*>(smraw);   // [8][NIBP]
        const int b = bid - WH_BLOCKS;
        const int bx = b & 7;
        const int ry = b >> 3;
        const int wi = t >> 5, lane = t & 31;
        const int r = ry * 8 + wi;
        const int4* rowp = reinterpret_cast<const int4*>(adj + (size_t)r * N + (size_t)bx * 1024);
        #pragma unroll
        for (int rd = 0; rd < 8; rd++) {
            const int4 v = rowp[rd * 32 + lane];
            unsigned nb = (v.x != 0) ? 1u : 0u;
            nb |= (v.y != 0) ? 2u : 0u;
            nb |= (v.z != 0) ? 4u : 0u;
            nb |= (v.w != 0) ? 8u : 0u;
            nib[wi * NIBP + rd * 32 + lane] = nb;
        }
        __syncthreads();
        const int word = t >> 3, row = t & 7;
        const uint4 nA = *reinterpret_cast<const uint4*>(nib + row * NIBP + word * 8);
        const uint4 nB = *reinterpret_cast<const uint4*>(nib + row * NIBP + word * 8 + 4);
        unsigned wv = nA.x | (nA.y << 4) | (nA.z << 8) | (nA.w << 12)
                    | (nB.x << 16) | (nB.y << 20) | (nB.z << 24) | (nB.w << 28);
        g_adjT[(size_t)(bx * 32 + word) * N + ry * 8 + row] = wv;
    }
}

// ================= K4: M=32/warp fp16 mma; ep computed inline =================
__global__ __launch_bounds__(256, 2) void gat_mma() {
    __shared__ __align__(16) uint4    smB[STAGES * 512];   // 4 x 8KB B
    __shared__ __align__(16) unsigned smA[STAGES * 512];   // 4 x 2KB adj words
    __shared__ __align__(16) uint2    ephs[JSPAN / 2];     // 4KB ep segment

    const int t = threadIdx.x;
    const int w = t >> 5, lane = t & 31;
    const int g = lane >> 2, tq = lane & 3;
    const int split = blockIdx.x;
    const int rowbase = blockIdx.y * TIROWS;
    const int jbase = split * JSPAN;
    const int kbg0 = jbase >> 4;
    const int wb0 = jbase >> 5;

    const float M2 = fdec(g_m2u);

    const int r1 = rowbase + w * 32 + g;       // set0: rows r1, r1+8
    const int r3 = r1 + 16;                    // set1: rows r3, r3+8
    const int rl = w * 32 + g;
    const uint2 ar1 = mk_ar(g_s1[r1], M2);
    const uint2 ar2 = mk_ar(g_s1[r1 + 8], M2);
    const uint2 ar3 = mk_ar(g_s1[r3], M2);
    const uint2 ar4 = mk_ar(g_s1[r3 + 8], M2);

    // compute this split's ep segment (2 j-pairs per thread)
    #pragma unroll
    for (int q = 0; q < 2; q++) {
        const int i2 = q * 256 + t;            // 0..511
        const float2 s2v = *reinterpret_cast<const float2*>(&g_s2[jbase + 2 * i2]);
        const float s2a = s2v.x - M2, s2b = s2v.y - M2;
        ephs[i2] = make_uint2(f16x2_pack(expf(s2a), expf(s2b)),
                              f16x2_pack(expf(0.5f * s2a), expf(0.5f * s2b)));
    }

    float acc0[8][4], acc1[8][4];
    #pragma unroll
    for (int nt = 0; nt < 8; nt++)
        #pragma unroll
        for (int c = 0; c < 4; c++) { acc0[nt][c] = 0.f; acc1[nt][c] = 0.f; }
    float accz0[4] = {0.f, 0.f, 0.f, 0.f};
    float accz1[4] = {0.f, 0.f, 0.f, 0.f};

    const uint4* bsrc4 = g_Bfrag + (size_t)kbg0 * 128;
    const uint32_t sbB = smem_u32(smB);
    const uint32_t sbA = smem_u32(smA);

    const int aq = t >> 6;
    const int arr = (t & 63) * 4;

    #pragma unroll
    for (int s = 0; s < STAGES - 1; s++) {
        CP16(sbB + s * 8192 + t * 16, bsrc4 + (size_t)s * 512 + t);
        CP16(sbB + s * 8192 + 4096 + t * 16, bsrc4 + (size_t)s * 512 + 256 + t);
        if (t < 128)
            CP16(sbA + s * 2048 + aq * 1024 + arr * 4,
                 g_adjT + (size_t)(wb0 + 2 * s + aq) * N + rowbase + arr);
        CP_COMMIT();
    }

    for (int hh = 0; hh < NIT; hh++) {
        const int slot = hh % STAGES;
        CP_WAIT(2);
        __syncthreads();

        if (hh + STAGES - 1 < NIT) {
            const int hs = hh + STAGES - 1;
            const int ns = hs % STAGES;
            CP16(sbB + ns * 8192 + t * 16, bsrc4 + (size_t)hs * 512 + t);
            CP16(sbB + ns * 8192 + 4096 + t * 16, bsrc4 + (size_t)hs * 512 + 256 + t);
            if (t < 128)
                CP16(sbA + ns * 2048 + aq * 1024 + arr * 4,
                     g_adjT + (size_t)(wb0 + 2 * hs + aq) * N + rowbase + arr);
        }
        CP_COMMIT();

        const uint4* bs = smB + slot * 512;
        const uint2* es = ephs + hh * 32;
        const unsigned* as = smA + slot * 512;

        unsigned cw[2][4];
        #pragma unroll
        for (int q = 0; q < 2; q++) {
            cw[q][0] = as[q * 256 + rl];
            cw[q][1] = as[q * 256 + rl + 8];
            cw[q][2] = as[q * 256 + rl + 16];
            cw[q][3] = as[q * 256 + rl + 24];
        }

        #pragma unroll
        for (int q = 0; q < 2; q++) {
            #pragma unroll
            for (int kb = 0; kb < 2; kb++) {
                const int kt = q * 2 + kb;
                uint32_t av0[4], av1[4];
                #pragma unroll
                for (int pr = 0; pr < 2; pr++) {
                    const int jloc = kb * 16 + pr * 8 + 2 * tq;
                    const uint2 e = es[kt * 8 + pr * 4 + tq];
                    const uint32_t e1h = hmul2(ar1.x, e.x), e1l = hmul2(ar1.y, e.y);
                    const uint32_t e2h = hmul2(ar2.x, e.x), e2l = hmul2(ar2.y, e.y);
                    const uint32_t e3h = hmul2(ar3.x, e.x), e3l = hmul2(ar3.y, e.y);
                    const uint32_t e4h = hmul2(ar4.x, e.x), e4l = hmul2(ar4.y, e.y);
                    av0[2 * pr + 0] = hmax2(e1h, e1l) & mk_mask2(cw[q][0], jloc);
                    av0[2 * pr + 1] = hmax2(e2h, e2l) & mk_mask2(cw[q][1], jloc);
                    av1[2 * pr + 0] = hmax2(e3h, e3l) & mk_mask2(cw[q][2], jloc);
                    av1[2 * pr + 1] = hmax2(e4h, e4l) & mk_mask2(cw[q][3], jloc);
                }
                #pragma unroll
                for (int ntp = 0; ntp < 4; ntp++) {
                    const uint4 b = bs[(kt * 4 + ntp) * 32 + lane];
                    MMA16816(acc0[2 * ntp + 0], av0[0], av0[1], av0[2], av0[3], b.x, b.y);
                    MMA16816(acc0[2 * ntp + 1], av0[0], av0[1], av0[2], av0[3], b.z, b.w);
                    MMA16816(acc1[2 * ntp + 0], av1[0], av1[1], av1[2], av1[3], b.x, b.y);
                    MMA16816(acc1[2 * ntp + 1], av1[0], av1[1], av1[2], av1[3], b.z, b.w);
                }
                MMA16816(accz0, av0[0], av0[1], av0[2], av0[3], ONES16, ONES16);
                MMA16816(accz1, av1[0], av1[1], av1[2], av1[3], ONES16, ONES16);
            }
        }
    }

    if (tq == 0) {
        g_Zp[split * N + r1]     = accz0[0];
        g_Zp[split * N + r1 + 8] = accz0[2];
        g_Zp[split * N + r3]     = accz1[0];
        g_Zp[split * N + r3 + 8] = accz1[2];
    }

    float* p1 = g_part + ((size_t)split * N + r1) * 64;
    float* p2 = g_part + ((size_t)split * N + r1 + 8) * 64;
    float* p3 = g_part + ((size_t)split * N + r3) * 64;
    float* p4 = g_part + ((size_t)split * N + r3 + 8) * 64;
    #pragma unroll
    for (int nt = 0; nt < 8; nt++) {
        const int c = nt * 8 + 2 * tq;
        *reinterpret_cast<float2*>(p1 + c) = make_float2(acc0[nt][0], acc0[nt][1]);
        *reinterpret_cast<float2*>(p2 + c) = make_float2(acc0[nt][2], acc0[nt][3]);
        *reinterpret_cast<float2*>(p3 + c) = make_float2(acc1[nt][0], acc1[nt][1]);
        *reinterpret_cast<float2*>(p4 + c) = make_float2(acc1[nt][2], acc1[nt][3]);
    }
}

// ================= K5: combine splits, normalize, relu =================
__global__ __launch_bounds__(256) void final_kernel(float* __restrict__ out) {
    const int idx = blockIdx.x * 256 + threadIdx.x;   // 8192*16 float4s
    const int row = idx >> 4;
    const int c4 = idx & 15;
    float z = 0.f;
    #pragma unroll
    for (int sp = 0; sp < NSPLIT; sp++) z += g_Zp[sp * N + row];
    const float inv = 1.f / z;
    const size_t off = (size_t)row * 64 + c4 * 4;
    float4 s = *reinterpret_cast<const float4*>(g_part + off);
    #pragma unroll
    for (int sp = 1; sp < NSPLIT; sp++) {
        const float4 p = *reinterpret_cast<const float4*>(g_part + (size_t)sp * N * 64 + off);
        s.x += p.x; s.y += p.y; s.z += p.z; s.w += p.w;
    }
    *reinterpret_cast<float4*>(out + off) = make_float4(
        fmaxf(s.x * inv, 0.f), fmaxf(s.y * inv, 0.f),
        fmaxf(s.z * inv, 0.f), fmaxf(s.w * inv, 0.f));
}

// ================= launch =================
extern "C" void kernel_launch(void* const* d_in, const int* in_sizes, int n_in,
                              void* d_out, int out_size) {
    const float* h   = (const float*)d_in[0];
    const int*   adj = (const int*)d_in[1];
    const float* W   = (const float*)d_in[2];
    const float* a   = (const float*)d_in[3];
    float*       out = (float*)d_out;

    fused0_kernel<<<WH_BLOCKS + BP_BLOCKS, 256>>>(h, W, a, adj);
    gat_mma<<<dim3(NSPLIT, N / TIROWS), 256>>>();
    final_kernel<<<(N * 16) / 256, 256>>>(out);
}